// round 9
// baseline (speedup 1.0000x reference)
#include <cuda_runtime.h>
#include <cuda_bf16.h>
#include <cstdint>

// Problem constants (fixed by the reference)
#define NS 100000
#define NP 20000
#define NE 500000
#define FH 128

// ---------------- device scratch (static allocation only) ----------------
__device__ float g_xplay[NP * FH];
__device__ float g_aggP [NP * FH];
__device__ float g_aggS [NS * FH];
__device__ float g_p1   [NP * FH];
__device__ float g_s1   [NS * FH];

__device__ int g_cntP[NP], g_curP[NP];
__device__ int g_cntS[NS], g_curS[NS];
__device__ int g_rpP[NP + 1];
__device__ int g_rpS[NS + 1];
__device__ int g_csrP[NE];   // song ids grouped by playlist
__device__ int g_csrS[NE];   // playlist ids grouped by song
__device__ int g_part[256];  // block partial sums for multi-block scan

// pre-split weights: 8 mats, each [n=128][k=128], bf16 hi + lo
__device__ __nv_bfloat16 g_whi[8 * FH * FH];
__device__ __nv_bfloat16 g_wlo[8 * FH * FH];

// ---------------- CSR build ----------------
__global__ void zero_misc_kernel() {
    int i = blockIdx.x * blockDim.x + threadIdx.x;
    if (i < NS) { g_cntS[i] = 0; g_curS[i] = 0; }
    if (i < NP) { g_cntP[i] = 0; g_curP[i] = 0; }
}

__global__ void hist_kernel(const int* __restrict__ es, const int* __restrict__ ep) {
    int i = blockIdx.x * blockDim.x + threadIdx.x;
    if (i < NE) {
        atomicAdd(&g_cntS[es[i]], 1);
        atomicAdd(&g_cntP[ep[i]], 1);
    }
}

// ---- multi-block exclusive scan: cnt[0..n) -> rowptr[0..n] ----
__global__ void scan1_kernel(const int* __restrict__ cnt, int* __restrict__ rowptr, int n) {
    __shared__ int s[512];
    int tid = threadIdx.x;
    int i = blockIdx.x * 512 + tid;
    int v = (i < n) ? cnt[i] : 0;
    s[tid] = v;
    __syncthreads();
#pragma unroll
    for (int off = 1; off < 512; off <<= 1) {
        int a = (tid >= off) ? s[tid - off] : 0;
        __syncthreads();
        s[tid] += a;
        __syncthreads();
    }
    if (i < n) rowptr[i] = s[tid] - v;
    if (tid == 511) g_part[blockIdx.x] = s[511];
}

__global__ void scan2_kernel(int nb) {
    __shared__ int s[256];
    int tid = threadIdx.x;
    s[tid] = (tid < nb) ? g_part[tid] : 0;
    __syncthreads();
#pragma unroll
    for (int off = 1; off < 256; off <<= 1) {
        int a = (tid >= off) ? s[tid - off] : 0;
        __syncthreads();
        s[tid] += a;
        __syncthreads();
    }
    if (tid < nb) g_part[tid] = s[tid];
}

__global__ void scan3_kernel(int* __restrict__ rowptr, int n, int nb) {
    int tid = threadIdx.x;
    int i = blockIdx.x * 512 + tid;
    if (i < n && blockIdx.x > 0) rowptr[i] += g_part[blockIdx.x - 1];
    if (i == 0) rowptr[n] = g_part[nb - 1];
}

__global__ void fill_kernel(const int* __restrict__ es, const int* __restrict__ ep) {
    int i = blockIdx.x * blockDim.x + threadIdx.x;
    if (i < NE) {
        int s = es[i], p = ep[i];
        int posP = atomicAdd(&g_curP[p], 1);
        g_csrP[g_rpP[p] + posP] = s;
        int posS = atomicAdd(&g_curS[s], 1);
        g_csrS[g_rpS[s] + posS] = p;
    }
}

// x_play = playlist_embed[playlist_node_id]
__global__ void gather_xplay_kernel(const float* __restrict__ pemb, const int* __restrict__ pid) {
    int i = blockIdx.x * blockDim.x + threadIdx.x;
    if (i < NP * 32) {
        int row = i >> 5;
        int q = i & 31;
        int src = pid[row];
        float4 v = *(const float4*)(pemb + (size_t)src * FH + q * 4);
        *(float4*)(g_xplay + (size_t)row * FH + q * 4) = v;
    }
}

// ---- weight pre-split: W[k][n] f32 -> hi/lo bf16 in [n][k] layout ----
__global__ void wsplit_kernel(const float* __restrict__ W,
                              __nv_bfloat16* __restrict__ hi,
                              __nv_bfloat16* __restrict__ lo) {
    int i = blockIdx.x * blockDim.x + threadIdx.x;   // 16384
    int k = i >> 7, n = i & 127;                     // coalesced read over n
    float w = W[k * FH + n];
    __nv_bfloat16 h = __float2bfloat16_rn(w);
    float hf = __bfloat162float(h);
    __nv_bfloat16 l = __float2bfloat16_rn(w - hf);
    hi[n * FH + k] = h;                              // [n][k]
    lo[n * FH + k] = l;
}

// ---------------- mean aggregation (warp per destination row) ----------------
__global__ void agg_mean_kernel(const float* __restrict__ src,
                                const int* __restrict__ rowptr,
                                const int* __restrict__ cols,
                                float* __restrict__ out, int nrows) {
    int warp = (blockIdx.x * blockDim.x + threadIdx.x) >> 5;
    int lane = threadIdx.x & 31;
    if (warp >= nrows) return;
    int beg = rowptr[warp], end = rowptr[warp + 1];
    float4 acc = make_float4(0.f, 0.f, 0.f, 0.f);
    int e = beg;
    for (; e + 3 < end; e += 4) {
        int c0 = cols[e], c1 = cols[e + 1], c2 = cols[e + 2], c3 = cols[e + 3];
        float4 v0 = *(const float4*)(src + (size_t)c0 * FH + lane * 4);
        float4 v1 = *(const float4*)(src + (size_t)c1 * FH + lane * 4);
        float4 v2 = *(const float4*)(src + (size_t)c2 * FH + lane * 4);
        float4 v3 = *(const float4*)(src + (size_t)c3 * FH + lane * 4);
        acc.x += (v0.x + v1.x) + (v2.x + v3.x);
        acc.y += (v0.y + v1.y) + (v2.y + v3.y);
        acc.z += (v0.z + v1.z) + (v2.z + v3.z);
        acc.w += (v0.w + v1.w) + (v2.w + v3.w);
    }
    for (; e < end; ++e) {
        int c0 = cols[e];
        float4 v0 = *(const float4*)(src + (size_t)c0 * FH + lane * 4);
        acc.x += v0.x; acc.y += v0.y; acc.z += v0.z; acc.w += v0.w;
    }
    int d = end - beg;
    float inv = 1.f / (float)(d > 0 ? d : 1);
    acc.x *= inv; acc.y *= inv; acc.z *= inv; acc.w *= inv;
    *(float4*)(out + (size_t)warp * FH + lane * 4) = acc;
}

// ---------------- 3xBF16 GEMM: out[M,128] = A0@W0 + A1@W1 + b (opt relu) ----------------
// A split to bf16 hi/lo at smem-store time; W pre-split in global ([n][k] bf16).
// mma.m16n8k16.row.col: hi*hi + hi*lo + lo*hi (lo*lo dropped, ~2^-18 rel).

__device__ __forceinline__ unsigned pack2bf(float f0, float f1) {
    // lower half = f0, upper half = f1
    unsigned r;
    asm("cvt.rn.bf16x2.f32 %0, %1, %2;" : "=r"(r) : "f"(f1), "f"(f0));
    return r;
}

#define MMA_BF16(acc, a, b0, b1)                                                   \
    asm volatile("mma.sync.aligned.m16n8k16.row.col.f32.bf16.bf16.f32 "            \
                 "{%0,%1,%2,%3},{%4,%5,%6,%7},{%8,%9},{%0,%1,%2,%3};"              \
                 : "+f"(acc[0]), "+f"(acc[1]), "+f"(acc[2]), "+f"(acc[3])          \
                 : "r"(a[0]), "r"(a[1]), "r"(a[2]), "r"(a[3]), "r"(b0), "r"(b1))

#define ALD 40   // bf16 elements per smem row (32 data + 8 pad) -> conflict-free frags

__global__ __launch_bounds__(256)
void gemm_bf16_kernel(const float* __restrict__ A0, const float* __restrict__ A1,
                      const __nv_bfloat16* __restrict__ Wh0, const __nv_bfloat16* __restrict__ Wl0,
                      const __nv_bfloat16* __restrict__ Wh1, const __nv_bfloat16* __restrict__ Wl1,
                      const float* __restrict__ bias,
                      float* __restrict__ out, int M, int do_relu) {
    __shared__ unsigned short Ah[128 * ALD], Al[128 * ALD];
    __shared__ unsigned short Bh[128 * ALD], Bl[128 * ALD];
    __shared__ float bias_s[128];

    int tid = threadIdx.x;
    int lane = tid & 31;
    int wid = tid >> 5;
    int warp_m = wid & 3;    // 4 warps along M (32 rows each)
    int warp_n = wid >> 2;   // 2 warps along N (64 cols each)
    int g = lane >> 2;       // groupID
    int r = lane & 3;        // thread in group
    int blockRow = blockIdx.x * 128;

    if (tid < 128) bias_s[tid] = bias[tid];

    float acc[2][8][4];
#pragma unroll
    for (int mt = 0; mt < 2; ++mt)
#pragma unroll
        for (int nt = 0; nt < 8; ++nt)
#pragma unroll
            for (int j = 0; j < 4; ++j) acc[mt][nt][j] = 0.f;

#pragma unroll
    for (int seg = 0; seg < 2; ++seg) {
        const float* Aseg = seg ? A1 : A0;
        const __nv_bfloat16* Whseg = seg ? Wh1 : Wh0;
        const __nv_bfloat16* Wlseg = seg ? Wl1 : Wl0;
#pragma unroll
        for (int kc = 0; kc < 4; ++kc) {
            __syncthreads();
            // ---- A tile [128 m x 32 k]: load f32, split to bf16 hi/lo, store packed ----
#pragma unroll
            for (int rr = 0; rr < 4; ++rr) {
                int idx = rr * 256 + tid;      // 1024 float4 slots
                int m = idx >> 3;
                int kq = idx & 7;              // float4 within the 32-k row
                int grow = blockRow + m;
                float4 v = make_float4(0.f, 0.f, 0.f, 0.f);
                if (grow < M)
                    v = *(const float4*)(Aseg + (size_t)grow * 128 + kc * 32 + kq * 4);
                unsigned h01 = pack2bf(v.x, v.y);
                unsigned h23 = pack2bf(v.z, v.w);
                float l0 = v.x - __uint_as_float(h01 << 16);
                float l1 = v.y - __uint_as_float(h01 & 0xffff0000u);
                float l2 = v.z - __uint_as_float(h23 << 16);
                float l3 = v.w - __uint_as_float(h23 & 0xffff0000u);
                unsigned lo01 = pack2bf(l0, l1);
                unsigned lo23 = pack2bf(l2, l3);
                unsigned off = m * ALD + kq * 4;   // bf16 units, 4B-aligned
                *(unsigned*)&Ah[off]     = h01;
                *(unsigned*)&Ah[off + 2] = h23;
                *(unsigned*)&Al[off]     = lo01;
                *(unsigned*)&Al[off + 2] = lo23;
            }
            // ---- B tile [128 n x 32 k]: straight copy of pre-split bf16 ----
#pragma unroll
            for (int rr = 0; rr < 2; ++rr) {
                int idx = rr * 256 + tid;      // 512 int4 slots (8 bf16 each)
                int n = idx >> 2;
                int kq = idx & 3;
                int4 vh = *(const int4*)((const unsigned short*)Whseg + n * FH + kc * 32 + kq * 8);
                int4 vl = *(const int4*)((const unsigned short*)Wlseg + n * FH + kc * 32 + kq * 8);
                unsigned off = n * ALD + kq * 8;   // 16B-aligned
                *(int4*)&Bh[off] = vh;
                *(int4*)&Bl[off] = vl;
            }
            __syncthreads();

            // ---- compute: 2 x k16 steps ----
#pragma unroll
            for (int k16 = 0; k16 < 2; ++k16) {
                int k0 = k16 * 16;
                unsigned ahi[2][4], alo[2][4];
#pragma unroll
                for (int mt = 0; mt < 2; ++mt) {
                    int mb = warp_m * 32 + mt * 16;
                    unsigned r0 = (mb + g) * ALD + k0 + 2 * r;
                    unsigned r1 = (mb + g + 8) * ALD + k0 + 2 * r;
                    ahi[mt][0] = *(const unsigned*)&Ah[r0];
                    ahi[mt][1] = *(const unsigned*)&Ah[r1];
                    ahi[mt][2] = *(const unsigned*)&Ah[r0 + 8];
                    ahi[mt][3] = *(const unsigned*)&Ah[r1 + 8];
                    alo[mt][0] = *(const unsigned*)&Al[r0];
                    alo[mt][1] = *(const unsigned*)&Al[r1];
                    alo[mt][2] = *(const unsigned*)&Al[r0 + 8];
                    alo[mt][3] = *(const unsigned*)&Al[r1 + 8];
                }
#pragma unroll
                for (int nt = 0; nt < 8; ++nt) {
                    int nb = warp_n * 64 + nt * 8;
                    unsigned rb = (nb + g) * ALD + k0 + 2 * r;
                    unsigned bh0 = *(const unsigned*)&Bh[rb];
                    unsigned bh1 = *(const unsigned*)&Bh[rb + 8];
                    unsigned bl0 = *(const unsigned*)&Bl[rb];
                    unsigned bl1 = *(const unsigned*)&Bl[rb + 8];
#pragma unroll
                    for (int mt = 0; mt < 2; ++mt) {
                        MMA_BF16(acc[mt][nt], ahi[mt], bh0, bh1);   // hi*hi
                        MMA_BF16(acc[mt][nt], ahi[mt], bl0, bl1);   // hi*lo
                        MMA_BF16(acc[mt][nt], alo[mt], bh0, bh1);   // lo*hi
                    }
                }
            }
        }
    }

    // epilogue (C layout of m16n8 identical to tf32 path)
#pragma unroll
    for (int mt = 0; mt < 2; ++mt) {
#pragma unroll
        for (int nt = 0; nt < 8; ++nt) {
            int col = warp_n * 64 + nt * 8 + r * 2;
            float bv0 = bias_s[col], bv1 = bias_s[col + 1];
            int row0 = blockRow + warp_m * 32 + mt * 16 + g;
            int row1 = row0 + 8;
            float v0 = acc[mt][nt][0] + bv0;
            float v1 = acc[mt][nt][1] + bv1;
            float v2 = acc[mt][nt][2] + bv0;
            float v3 = acc[mt][nt][3] + bv1;
            if (do_relu) {
                v0 = fmaxf(v0, 0.f); v1 = fmaxf(v1, 0.f);
                v2 = fmaxf(v2, 0.f); v3 = fmaxf(v3, 0.f);
            }
            if (row0 < M) *(float2*)(out + (size_t)row0 * 128 + col) = make_float2(v0, v1);
            if (row1 < M) *(float2*)(out + (size_t)row1 * 128 + col) = make_float2(v2, v3);
        }
    }
}

// ---------------- host launcher ----------------
static float* sym_f(const void* s) { void* p = nullptr; cudaGetSymbolAddress(&p, s); return (float*)p; }
static int*   sym_i(const void* s) { void* p = nullptr; cudaGetSymbolAddress(&p, s); return (int*)p; }
static __nv_bfloat16* sym_b(const void* s) { void* p = nullptr; cudaGetSymbolAddress(&p, s); return (__nv_bfloat16*)p; }

extern "C" void kernel_launch(void* const* d_in, const int* in_sizes, int n_in,
                              void* d_out, int out_size) {
    const float* song_x  = (const float*)d_in[0];
    const int*   pid     = (const int*)d_in[1];
    const int*   e_song  = (const int*)d_in[2];
    const int*   e_play  = (const int*)d_in[3];
    const float* pemb    = (const float*)d_in[4];
    const float* W[8] = {
        (const float*)d_in[5],  (const float*)d_in[6],   // Wl1_sp, Wr1_sp
        (const float*)d_in[8],  (const float*)d_in[9],   // Wl1_ps, Wr1_ps
        (const float*)d_in[11], (const float*)d_in[12],  // Wl2_sp, Wr2_sp
        (const float*)d_in[14], (const float*)d_in[15],  // Wl2_ps, Wr2_ps
    };
    const float* b1_sp = (const float*)d_in[7];
    const float* b1_ps = (const float*)d_in[10];
    const float* b2_sp = (const float*)d_in[13];
    const float* b2_ps = (const float*)d_in[16];

    float* out = (float*)d_out;
    float* out_s2 = out;                      // [NS,128] first
    float* out_p2 = out + (size_t)NS * FH;    // [NP,128] second

    float* xplay = sym_f(g_xplay);
    float* aggP  = sym_f(g_aggP);
    float* aggS  = sym_f(g_aggS);
    float* p1    = sym_f(g_p1);
    float* s1    = sym_f(g_s1);
    int*   cntP  = sym_i(g_cntP);
    int*   cntS  = sym_i(g_cntS);
    int*   rpP   = sym_i(g_rpP);
    int*   rpS   = sym_i(g_rpS);
    int*   csrP  = sym_i(g_csrP);
    int*   csrS  = sym_i(g_csrS);
    __nv_bfloat16* whi = sym_b(g_whi);
    __nv_bfloat16* wlo = sym_b(g_wlo);

    // ---- weight pre-split (independent of CSR) ----
    for (int i = 0; i < 8; ++i)
        wsplit_kernel<<<64, 256>>>(W[i], whi + i * FH * FH, wlo + i * FH * FH);

    // ---- CSR build (shared by both layers) ----
    zero_misc_kernel<<<(NS + 255) / 256, 256>>>();
    hist_kernel<<<(NE + 255) / 256, 256>>>(e_song, e_play);

    int nbP = (NP + 511) / 512;
    scan1_kernel<<<nbP, 512>>>(cntP, rpP, NP);
    scan2_kernel<<<1, 256>>>(nbP);
    scan3_kernel<<<nbP, 512>>>(rpP, NP, nbP);

    int nbS = (NS + 511) / 512;
    scan1_kernel<<<nbS, 512>>>(cntS, rpS, NS);
    scan2_kernel<<<1, 256>>>(nbS);
    scan3_kernel<<<nbS, 512>>>(rpS, NS, nbS);

    fill_kernel<<<(NE + 255) / 256, 256>>>(e_song, e_play);
    gather_xplay_kernel<<<(NP * 32 + 255) / 256, 256>>>(pemb, pid);

    const int AGG_WPB = 8;
#define WH(i) (whi + (i) * FH * FH)
#define WL(i) (wlo + (i) * FH * FH)
    // ---- conv1 ----
    agg_mean_kernel<<<(NP + AGG_WPB - 1) / AGG_WPB, AGG_WPB * 32>>>(song_x, rpP, csrP, aggP, NP);
    gemm_bf16_kernel<<<(NP + 127) / 128, 256>>>(aggP, xplay, WH(0), WL(0), WH(1), WL(1), b1_sp, p1, NP, 1);
    agg_mean_kernel<<<(NS + AGG_WPB - 1) / AGG_WPB, AGG_WPB * 32>>>(xplay, rpS, csrS, aggS, NS);
    gemm_bf16_kernel<<<(NS + 127) / 128, 256>>>(aggS, song_x, WH(2), WL(2), WH(3), WL(3), b1_ps, s1, NS, 1);

    // ---- conv2 ----
    agg_mean_kernel<<<(NP + AGG_WPB - 1) / AGG_WPB, AGG_WPB * 32>>>(s1, rpP, csrP, aggP, NP);
    gemm_bf16_kernel<<<(NP + 127) / 128, 256>>>(aggP, p1, WH(4), WL(4), WH(5), WL(5), b2_sp, out_p2, NP, 0);
    agg_mean_kernel<<<(NS + AGG_WPB - 1) / AGG_WPB, AGG_WPB * 32>>>(p1, rpS, csrS, aggS, NS);
    gemm_bf16_kernel<<<(NS + 127) / 128, 256>>>(aggS, s1, WH(6), WL(6), WH(7), WL(7), b2_ps, out_s2, NS, 0);
#undef WH
#undef WL

    (void)in_sizes; (void)n_in; (void)out_size;
}

// round 10
// speedup vs baseline: 1.4919x; 1.4919x over previous
#include <cuda_runtime.h>
#include <cuda_bf16.h>
#include <cstdint>

// Problem constants (fixed by the reference)
#define NS 100000
#define NP 20000
#define NE 500000
#define FH 128

// ---------------- device scratch (static allocation only) ----------------
__device__ float g_xplay[NP * FH];
__device__ float g_aggP [NP * FH];
__device__ float g_aggS [NS * FH];
__device__ float g_p1   [NP * FH];
__device__ float g_s1   [NS * FH];

__device__ int g_cntP[NP], g_curP[NP];
__device__ int g_cntS[NS], g_curS[NS];
__device__ int g_rpP[NP + 1];
__device__ int g_rpS[NS + 1];
__device__ int g_csrP[NE];    // song ids grouped by playlist
__device__ int g_csrS[NE];    // playlist ids grouped by song
__device__ int g_partP[256];  // block partials for P scan
__device__ int g_partS[256];  // block partials for S scan

// pre-split weights: 8 mats, each [n=128][k=128], bf16 hi + lo
__device__ __nv_bfloat16 g_whi[8 * FH * FH];
__device__ __nv_bfloat16 g_wlo[8 * FH * FH];

// ---------------- CSR build ----------------
__global__ void zero_misc_kernel() {
    int i = blockIdx.x * blockDim.x + threadIdx.x;
    if (i < NS) { g_cntS[i] = 0; g_curS[i] = 0; }
    if (i < NP) { g_cntP[i] = 0; g_curP[i] = 0; }
}

__global__ void hist_kernel(const int* __restrict__ es, const int* __restrict__ ep) {
    int i = blockIdx.x * blockDim.x + threadIdx.x;
    if (i < NE) {
        atomicAdd(&g_cntS[es[i]], 1);
        atomicAdd(&g_cntP[ep[i]], 1);
    }
}

// ---- fused multi-block exclusive scans (P in blocks [0,nbP), S in [nbP,nbP+nbS)) ----
__global__ void scan1_both_kernel(int nbP) {
    __shared__ int s[512];
    int tid = threadIdx.x;
    bool isP = (blockIdx.x < (unsigned)nbP);
    int blk = isP ? blockIdx.x : (blockIdx.x - nbP);
    const int* cnt = isP ? g_cntP : g_cntS;
    int* rowptr    = isP ? g_rpP  : g_rpS;
    int* part      = isP ? g_partP : g_partS;
    int n          = isP ? NP : NS;
    int i = blk * 512 + tid;
    int v = (i < n) ? cnt[i] : 0;
    s[tid] = v;
    __syncthreads();
#pragma unroll
    for (int off = 1; off < 512; off <<= 1) {
        int a = (tid >= off) ? s[tid - off] : 0;
        __syncthreads();
        s[tid] += a;
        __syncthreads();
    }
    if (i < n) rowptr[i] = s[tid] - v;
    if (tid == 511) part[blk] = s[511];
}

__global__ void scan2_both_kernel(int nbP, int nbS) {
    __shared__ int s[256];
    int tid = threadIdx.x;
    int* part = (blockIdx.x == 0) ? g_partP : g_partS;
    int nb    = (blockIdx.x == 0) ? nbP : nbS;
    s[tid] = (tid < nb) ? part[tid] : 0;
    __syncthreads();
#pragma unroll
    for (int off = 1; off < 256; off <<= 1) {
        int a = (tid >= off) ? s[tid - off] : 0;
        __syncthreads();
        s[tid] += a;
        __syncthreads();
    }
    if (tid < nb) part[tid] = s[tid];
}

__global__ void scan3_both_kernel(int nbP, int nbS) {
    int tid = threadIdx.x;
    bool isP = (blockIdx.x < (unsigned)nbP);
    int blk = isP ? blockIdx.x : (blockIdx.x - nbP);
    int* rowptr = isP ? g_rpP : g_rpS;
    int* part   = isP ? g_partP : g_partS;
    int n       = isP ? NP : NS;
    int nb      = isP ? nbP : nbS;
    int i = blk * 512 + tid;
    if (i < n && blk > 0) rowptr[i] += part[blk - 1];
    if (i == 0) rowptr[n] = part[nb - 1];
}

__global__ void fill_kernel(const int* __restrict__ es, const int* __restrict__ ep) {
    int i = blockIdx.x * blockDim.x + threadIdx.x;
    if (i < NE) {
        int s = es[i], p = ep[i];
        int posP = atomicAdd(&g_curP[p], 1);
        g_csrP[g_rpP[p] + posP] = s;
        int posS = atomicAdd(&g_curS[s], 1);
        g_csrS[g_rpS[s] + posS] = p;
    }
}

// x_play = playlist_embed[playlist_node_id]
__global__ void gather_xplay_kernel(const float* __restrict__ pemb, const int* __restrict__ pid) {
    int i = blockIdx.x * blockDim.x + threadIdx.x;
    if (i < NP * 32) {
        int row = i >> 5;
        int q = i & 31;
        int src = pid[row];
        float4 v = *(const float4*)(pemb + (size_t)src * FH + q * 4);
        *(float4*)(g_xplay + (size_t)row * FH + q * 4) = v;
    }
}

// ---- fused weight pre-split: all 8 mats in one launch ----
struct WsplitArgs { const float* W[8]; };
__global__ void wsplit_all_kernel(WsplitArgs args) {
    int mat = blockIdx.x >> 6;                        // 64 blocks per matrix
    int i = (blockIdx.x & 63) * 256 + threadIdx.x;    // 0..16383
    int k = i >> 7, n = i & 127;
    float w = args.W[mat][k * FH + n];
    __nv_bfloat16 h = __float2bfloat16_rn(w);
    float hf = __bfloat162float(h);
    __nv_bfloat16 l = __float2bfloat16_rn(w - hf);
    g_whi[mat * FH * FH + n * FH + k] = h;            // [n][k]
    g_wlo[mat * FH * FH + n * FH + k] = l;
}

// ---------------- fused mean aggregation: P-dest rows then S-dest rows ----------------
struct AggArgs {
    const float* srcP;   // messages into playlists
    const float* srcS;   // messages into songs
    float* outP;
    float* outS;
};
__global__ void agg_both_kernel(AggArgs a) {
    int warp = (blockIdx.x * blockDim.x + threadIdx.x) >> 5;
    int lane = threadIdx.x & 31;
    const float* src;
    const int* rowptr;
    const int* cols;
    float* out;
    int row;
    if (warp < NP) {
        src = a.srcP; rowptr = g_rpP; cols = g_csrP; out = a.outP; row = warp;
    } else if (warp < NP + NS) {
        src = a.srcS; rowptr = g_rpS; cols = g_csrS; out = a.outS; row = warp - NP;
    } else return;
    int beg = rowptr[row], end = rowptr[row + 1];
    float4 acc = make_float4(0.f, 0.f, 0.f, 0.f);
    int e = beg;
    for (; e + 3 < end; e += 4) {
        int c0 = cols[e], c1 = cols[e + 1], c2 = cols[e + 2], c3 = cols[e + 3];
        float4 v0 = *(const float4*)(src + (size_t)c0 * FH + lane * 4);
        float4 v1 = *(const float4*)(src + (size_t)c1 * FH + lane * 4);
        float4 v2 = *(const float4*)(src + (size_t)c2 * FH + lane * 4);
        float4 v3 = *(const float4*)(src + (size_t)c3 * FH + lane * 4);
        acc.x += (v0.x + v1.x) + (v2.x + v3.x);
        acc.y += (v0.y + v1.y) + (v2.y + v3.y);
        acc.z += (v0.z + v1.z) + (v2.z + v3.z);
        acc.w += (v0.w + v1.w) + (v2.w + v3.w);
    }
    for (; e < end; ++e) {
        int c0 = cols[e];
        float4 v0 = *(const float4*)(src + (size_t)c0 * FH + lane * 4);
        acc.x += v0.x; acc.y += v0.y; acc.z += v0.z; acc.w += v0.w;
    }
    int d = end - beg;
    float inv = 1.f / (float)(d > 0 ? d : 1);
    acc.x *= inv; acc.y *= inv; acc.z *= inv; acc.w *= inv;
    *(float4*)(out + (size_t)row * FH + lane * 4) = acc;
}

// ---------------- fused 3xBF16 GEMM pair ----------------
// Each sub-problem: out[M,128] = A0@W0 + A1@W1 + b (opt relu)
// A split to bf16 hi/lo at smem-store time; W pre-split ([n][k] bf16 hi/lo).
// hi*hi + hi*lo + lo*hi (lo*lo dropped, ~2^-18 rel).

__device__ __forceinline__ unsigned pack2bf(float f0, float f1) {
    unsigned r;
    asm("cvt.rn.bf16x2.f32 %0, %1, %2;" : "=r"(r) : "f"(f1), "f"(f0));
    return r;
}

#define MMA_BF16(acc, a, b0, b1)                                                   \
    asm volatile("mma.sync.aligned.m16n8k16.row.col.f32.bf16.bf16.f32 "            \
                 "{%0,%1,%2,%3},{%4,%5,%6,%7},{%8,%9},{%0,%1,%2,%3};"              \
                 : "+f"(acc[0]), "+f"(acc[1]), "+f"(acc[2]), "+f"(acc[3])          \
                 : "r"(a[0]), "r"(a[1]), "r"(a[2]), "r"(a[3]), "r"(b0), "r"(b1))

#define ALD 40   // bf16 elements per smem row (32 data + 8 pad) -> conflict-free frags

struct GemmSub {
    const float* A0;
    const float* A1;
    const __nv_bfloat16 *Wh0, *Wl0, *Wh1, *Wl1;
    const float* bias;
    float* out;
    int M;
    int relu;
};
struct GemmPairArgs { GemmSub s[2]; int gridA; };

__global__ __launch_bounds__(256)
void gemm_pair_kernel(GemmPairArgs args) {
    __shared__ unsigned short Ah[128 * ALD], Al[128 * ALD];
    __shared__ unsigned short Bh[128 * ALD], Bl[128 * ALD];
    __shared__ float bias_s[128];

    int which = (blockIdx.x < (unsigned)args.gridA) ? 0 : 1;
    const GemmSub& P = args.s[which];
    int blockRow = (which ? (blockIdx.x - args.gridA) : blockIdx.x) * 128;
    int M = P.M;
    int do_relu = P.relu;

    int tid = threadIdx.x;
    int lane = tid & 31;
    int wid = tid >> 5;
    int warp_m = wid & 3;    // 4 warps along M (32 rows each)
    int warp_n = wid >> 2;   // 2 warps along N (64 cols each)
    int g = lane >> 2;
    int r = lane & 3;

    if (tid < 128) bias_s[tid] = P.bias[tid];

    float acc[2][8][4];
#pragma unroll
    for (int mt = 0; mt < 2; ++mt)
#pragma unroll
        for (int nt = 0; nt < 8; ++nt)
#pragma unroll
            for (int j = 0; j < 4; ++j) acc[mt][nt][j] = 0.f;

#pragma unroll
    for (int seg = 0; seg < 2; ++seg) {
        const float* Aseg = seg ? P.A1 : P.A0;
        const __nv_bfloat16* Whseg = seg ? P.Wh1 : P.Wh0;
        const __nv_bfloat16* Wlseg = seg ? P.Wl1 : P.Wl0;
#pragma unroll
        for (int kc = 0; kc < 4; ++kc) {
            __syncthreads();
            // ---- A tile [128 m x 32 k]: load f32, split to bf16 hi/lo ----
#pragma unroll
            for (int rr = 0; rr < 4; ++rr) {
                int idx = rr * 256 + tid;
                int m = idx >> 3;
                int kq = idx & 7;
                int grow = blockRow + m;
                float4 v = make_float4(0.f, 0.f, 0.f, 0.f);
                if (grow < M)
                    v = *(const float4*)(Aseg + (size_t)grow * 128 + kc * 32 + kq * 4);
                unsigned h01 = pack2bf(v.x, v.y);
                unsigned h23 = pack2bf(v.z, v.w);
                float l0 = v.x - __uint_as_float(h01 << 16);
                float l1 = v.y - __uint_as_float(h01 & 0xffff0000u);
                float l2 = v.z - __uint_as_float(h23 << 16);
                float l3 = v.w - __uint_as_float(h23 & 0xffff0000u);
                unsigned lo01 = pack2bf(l0, l1);
                unsigned lo23 = pack2bf(l2, l3);
                unsigned off = m * ALD + kq * 4;
                *(unsigned*)&Ah[off]     = h01;
                *(unsigned*)&Ah[off + 2] = h23;
                *(unsigned*)&Al[off]     = lo01;
                *(unsigned*)&Al[off + 2] = lo23;
            }
            // ---- B tile [128 n x 32 k]: straight copy of pre-split bf16 ----
#pragma unroll
            for (int rr = 0; rr < 2; ++rr) {
                int idx = rr * 256 + tid;
                int n = idx >> 2;
                int kq = idx & 3;
                int4 vh = *(const int4*)((const unsigned short*)Whseg + n * FH + kc * 32 + kq * 8);
                int4 vl = *(const int4*)((const unsigned short*)Wlseg + n * FH + kc * 32 + kq * 8);
                unsigned off = n * ALD + kq * 8;
                *(int4*)&Bh[off] = vh;
                *(int4*)&Bl[off] = vl;
            }
            __syncthreads();

            // ---- compute: 2 x k16 steps ----
#pragma unroll
            for (int k16 = 0; k16 < 2; ++k16) {
                int k0 = k16 * 16;
                unsigned ahi[2][4], alo[2][4];
#pragma unroll
                for (int mt = 0; mt < 2; ++mt) {
                    int mb = warp_m * 32 + mt * 16;
                    unsigned r0 = (mb + g) * ALD + k0 + 2 * r;
                    unsigned r1 = (mb + g + 8) * ALD + k0 + 2 * r;
                    ahi[mt][0] = *(const unsigned*)&Ah[r0];
                    ahi[mt][1] = *(const unsigned*)&Ah[r1];
                    ahi[mt][2] = *(const unsigned*)&Ah[r0 + 8];
                    ahi[mt][3] = *(const unsigned*)&Ah[r1 + 8];
                    alo[mt][0] = *(const unsigned*)&Al[r0];
                    alo[mt][1] = *(const unsigned*)&Al[r1];
                    alo[mt][2] = *(const unsigned*)&Al[r0 + 8];
                    alo[mt][3] = *(const unsigned*)&Al[r1 + 8];
                }
#pragma unroll
                for (int nt = 0; nt < 8; ++nt) {
                    int nb = warp_n * 64 + nt * 8;
                    unsigned rb = (nb + g) * ALD + k0 + 2 * r;
                    unsigned bh0 = *(const unsigned*)&Bh[rb];
                    unsigned bh1 = *(const unsigned*)&Bh[rb + 8];
                    unsigned bl0 = *(const unsigned*)&Bl[rb];
                    unsigned bl1 = *(const unsigned*)&Bl[rb + 8];
#pragma unroll
                    for (int mt = 0; mt < 2; ++mt) {
                        MMA_BF16(acc[mt][nt], ahi[mt], bh0, bh1);   // hi*hi
                        MMA_BF16(acc[mt][nt], ahi[mt], bl0, bl1);   // hi*lo
                        MMA_BF16(acc[mt][nt], alo[mt], bh0, bh1);   // lo*hi
                    }
                }
            }
        }
    }

    // epilogue
#pragma unroll
    for (int mt = 0; mt < 2; ++mt) {
#pragma unroll
        for (int nt = 0; nt < 8; ++nt) {
            int col = warp_n * 64 + nt * 8 + r * 2;
            float bv0 = bias_s[col], bv1 = bias_s[col + 1];
            int row0 = blockRow + warp_m * 32 + mt * 16 + g;
            int row1 = row0 + 8;
            float v0 = acc[mt][nt][0] + bv0;
            float v1 = acc[mt][nt][1] + bv1;
            float v2 = acc[mt][nt][2] + bv0;
            float v3 = acc[mt][nt][3] + bv1;
            if (do_relu) {
                v0 = fmaxf(v0, 0.f); v1 = fmaxf(v1, 0.f);
                v2 = fmaxf(v2, 0.f); v3 = fmaxf(v3, 0.f);
            }
            if (row0 < M) *(float2*)(P.out + (size_t)row0 * 128 + col) = make_float2(v0, v1);
            if (row1 < M) *(float2*)(P.out + (size_t)row1 * 128 + col) = make_float2(v2, v3);
        }
    }
}

// ---------------- host launcher ----------------
static float* sym_f(const void* s) { void* p = nullptr; cudaGetSymbolAddress(&p, s); return (float*)p; }
static __nv_bfloat16* sym_b(const void* s) { void* p = nullptr; cudaGetSymbolAddress(&p, s); return (__nv_bfloat16*)p; }

extern "C" void kernel_launch(void* const* d_in, const int* in_sizes, int n_in,
                              void* d_out, int out_size) {
    const float* song_x  = (const float*)d_in[0];
    const int*   pid     = (const int*)d_in[1];
    const int*   e_song  = (const int*)d_in[2];
    const int*   e_play  = (const int*)d_in[3];
    const float* pemb    = (const float*)d_in[4];
    const float* b1_sp = (const float*)d_in[7];
    const float* b1_ps = (const float*)d_in[10];
    const float* b2_sp = (const float*)d_in[13];
    const float* b2_ps = (const float*)d_in[16];

    float* out = (float*)d_out;
    float* out_s2 = out;                      // [NS,128] first
    float* out_p2 = out + (size_t)NS * FH;    // [NP,128] second

    float* xplay = sym_f(g_xplay);
    float* aggP  = sym_f(g_aggP);
    float* aggS  = sym_f(g_aggS);
    float* p1    = sym_f(g_p1);
    float* s1    = sym_f(g_s1);
    __nv_bfloat16* whi = sym_b(g_whi);
    __nv_bfloat16* wlo = sym_b(g_wlo);

    // ---- weight pre-split: single launch for all 8 matrices ----
    WsplitArgs wa;
    wa.W[0] = (const float*)d_in[5];   // Wl1_sp
    wa.W[1] = (const float*)d_in[6];   // Wr1_sp
    wa.W[2] = (const float*)d_in[8];   // Wl1_ps
    wa.W[3] = (const float*)d_in[9];   // Wr1_ps
    wa.W[4] = (const float*)d_in[11];  // Wl2_sp
    wa.W[5] = (const float*)d_in[12];  // Wr2_sp
    wa.W[6] = (const float*)d_in[14];  // Wl2_ps
    wa.W[7] = (const float*)d_in[15];  // Wr2_ps
    wsplit_all_kernel<<<512, 256>>>(wa);

    // ---- CSR build ----
    zero_misc_kernel<<<(NS + 255) / 256, 256>>>();
    hist_kernel<<<(NE + 255) / 256, 256>>>(e_song, e_play);

    int nbP = (NP + 511) / 512;   // 40
    int nbS = (NS + 511) / 512;   // 196
    scan1_both_kernel<<<nbP + nbS, 512>>>(nbP);
    scan2_both_kernel<<<2, 256>>>(nbP, nbS);
    scan3_both_kernel<<<nbP + nbS, 512>>>(nbP, nbS);

    fill_kernel<<<(NE + 255) / 256, 256>>>(e_song, e_play);
    gather_xplay_kernel<<<(NP * 32 + 255) / 256, 256>>>(pemb, pid);

    const int AGG_WPB = 8;
    const int AGG_GRID = (NP + NS + AGG_WPB - 1) / AGG_WPB;
    int gridA = (NP + 127) / 128;   // 157
    int gridB = (NS + 127) / 128;   // 782

#define WH(i) (whi + (i) * FH * FH)
#define WL(i) (wlo + (i) * FH * FH)
    // ---- conv1 ----
    {
        AggArgs a{song_x, xplay, aggP, aggS};
        agg_both_kernel<<<AGG_GRID, AGG_WPB * 32>>>(a);
        GemmPairArgs ga;
        ga.s[0] = {aggP, xplay, WH(0), WL(0), WH(1), WL(1), b1_sp, p1, NP, 1};
        ga.s[1] = {aggS, song_x, WH(2), WL(2), WH(3), WL(3), b1_ps, s1, NS, 1};
        ga.gridA = gridA;
        gemm_pair_kernel<<<gridA + gridB, 256>>>(ga);
    }
    // ---- conv2 ----
    {
        AggArgs a{s1, p1, aggP, aggS};
        agg_both_kernel<<<AGG_GRID, AGG_WPB * 32>>>(a);
        GemmPairArgs ga;
        ga.s[0] = {aggP, p1, WH(4), WL(4), WH(5), WL(5), b2_sp, out_p2, NP, 0};
        ga.s[1] = {aggS, s1, WH(6), WL(6), WH(7), WL(7), b2_ps, out_s2, NS, 0};
        ga.gridA = gridA;
        gemm_pair_kernel<<<gridA + gridB, 256>>>(ga);
    }
#undef WH
#undef WL

    (void)in_sizes; (void)n_in; (void)out_size;
}